// round 14
// baseline (speedup 1.0000x reference)
#include <cuda_runtime.h>
#include <cuda_fp16.h>
#include <math.h>
#include <stdint.h>

#define NB   4096
#define NE   16
#define DI   1024
#define DH   2048
#define DOUT 1024
#define NSLOT (NB * 2)
#define MAXT 80            // max 128-row m-tiles across experts (<=79, pad 80)
#define NT1  (DH / 128)    // 16 n-tiles in GEMM1
#define NT2  (DOUT / 128)  // 8 n-tiles in GEMM2
#define T1TOT (MAXT * NT1) // 1280
#define NSCAT (NB / 256)   // 16 scatter tickets
#define TTOT  (NSCAT + MAXT * (NT1 + NT2))
#define NCTA  296          // 2 CTAs per SM x 148 SMs
#define ZB   256           // out-zero blocks appended to gate grid
#define GTOK 8             // tokens per gate block

// ---------------- scratch ----------------------------------------------------
__device__ __half g_h[(size_t)NSLOT * DH];
__device__ int    g_perm[NSLOT];
__device__ int    g_counts[NE];
__device__ int    g_cursor[NE];
__device__ int    g_off[NE + 1];
__device__ int    g_tidx[NB * 2];
__device__ float  g_tw[NB * 2];
__device__ int    g_tile_e[MAXT];
__device__ int    g_tile_m[MAXT];
__device__ int    g_done[MAXT];
__device__ int    g_ticket;
__device__ int    g_gatefin;
__device__ int    g_scat;
__device__ int    g_finish;

// ---------------- helpers ----------------------------------------------------
__device__ __forceinline__ void ldsm4(uint32_t addr, uint32_t* a) {
    asm volatile("ldmatrix.sync.aligned.m8n8.x4.shared.b16 {%0,%1,%2,%3}, [%4];"
                 : "=r"(a[0]), "=r"(a[1]), "=r"(a[2]), "=r"(a[3]) : "r"(addr));
}
__device__ __forceinline__ void mma_f16(float* d, const uint32_t* a, const uint32_t* b) {
    asm volatile(
        "mma.sync.aligned.m16n8k16.row.col.f32.f16.f16.f32 "
        "{%0,%1,%2,%3}, {%4,%5,%6,%7}, {%8,%9}, {%0,%1,%2,%3};"
        : "+f"(d[0]), "+f"(d[1]), "+f"(d[2]), "+f"(d[3])
        : "r"(a[0]), "r"(a[1]), "r"(a[2]), "r"(a[3]), "r"(b[0]), "r"(b[1]));
}
__device__ __forceinline__ uint32_t h2bits(__half2 h) {
    return *reinterpret_cast<uint32_t*>(&h);
}
__device__ __forceinline__ uint2 cvt2h(float4 v) {
    uint2 u;
    u.x = h2bits(__floats2half2_rn(v.x, v.y));
    u.y = h2bits(__floats2half2_rn(v.z, v.w));
    return u;
}
__device__ __forceinline__ void red2(float* p, float a, float b) {
    asm volatile("red.global.add.v2.f32 [%0], {%1, %2};"
                 :: "l"(p), "f"(a), "f"(b) : "memory");
}

// ---------------- gate (fp32 exact) + co-scheduled out-zeroing ----------------
// blocks [0, NB/GTOK): gating, 8 tokens each. blocks [NB/GTOK, +ZB): zero out.
// Control state was reset by the previous moe_gemm's last CTA.
__global__ __launch_bounds__(128) void gate_kernel(const float* __restrict__ x,
                                                   const float* __restrict__ gw,
                                                   float* __restrict__ out) {
    if (blockIdx.x >= NB / GTOK) {
        int c = blockIdx.x - NB / GTOK;
        float4* o4 = (float4*)out;
        int base = c * 128 + threadIdx.x;
        const int STRIDE = ZB * 128;
        #pragma unroll 8
        for (int i = 0; i < (NB * DOUT / 4) / (ZB * 128); ++i)
            o4[base + i * STRIDE] = make_float4(0.f, 0.f, 0.f, 0.f);
        return;
    }

    __shared__ float xs[GTOK][DI];        // 32KB
    __shared__ float sc[GTOK][NE];
    __shared__ int s_last;
    int t0 = blockIdx.x * GTOK;

    const float4* xsrc = (const float4*)(x + (size_t)t0 * DI);
    float4* xd = (float4*)&xs[0][0];
    #pragma unroll 4
    for (int i = threadIdx.x; i < GTOK * DI / 4; i += 128) xd[i] = xsrc[i];
    __syncthreads();

    int warp = threadIdx.x >> 5, lane = threadIdx.x & 31;
    for (int e = warp * 4; e < warp * 4 + 4; ++e) {
        float s[GTOK];
        #pragma unroll
        for (int t = 0; t < GTOK; ++t) s[t] = 0.f;
        for (int i = lane; i < DI; i += 32) {
            float g = gw[e * DI + i];
            #pragma unroll
            for (int t = 0; t < GTOK; ++t) s[t] += xs[t][i] * g;
        }
        #pragma unroll
        for (int o = 16; o > 0; o >>= 1) {
            #pragma unroll
            for (int t = 0; t < GTOK; ++t)
                s[t] += __shfl_xor_sync(0xffffffffu, s[t], o);
        }
        if (lane == 0) {
            #pragma unroll
            for (int t = 0; t < GTOK; ++t) sc[t][e] = s[t];
        }
    }
    __syncthreads();

    if (threadIdx.x < GTOK) {
        int tt = threadIdx.x;
        int tok = t0 + tt;
        float bv = -1e30f; int bi = 0;
        #pragma unroll
        for (int e = 0; e < NE; ++e) {
            float v = sc[tt][e];
            if (v > bv) { bv = v; bi = e; }
        }
        float bv2 = -1e30f; int bi2 = 0;
        #pragma unroll
        for (int e = 0; e < NE; ++e) {
            if (e == bi) continue;
            float v = sc[tt][e];
            if (v > bv2) { bv2 = v; bi2 = e; }
        }
        float e2 = expf(bv2 - bv);
        float inv = 1.0f / (1.0f + e2);
        g_tidx[tok * 2 + 0] = bi;  g_tw[tok * 2 + 0] = inv;
        g_tidx[tok * 2 + 1] = bi2; g_tw[tok * 2 + 1] = e2 * inv;
        atomicAdd(&g_counts[bi], 1);
        atomicAdd(&g_counts[bi2], 1);
    }

    // last finished gate block computes prefix sums + tile table
    __threadfence();
    __syncthreads();
    if (threadIdx.x == 0)
        s_last = (atomicAdd(&g_gatefin, 1) == NB / GTOK - 1) ? 1 : 0;
    __syncthreads();
    if (s_last && threadIdx.x == 0) {
        int s = 0;
        #pragma unroll
        for (int e = 0; e < NE; ++e) { g_off[e] = s; s += g_counts[e]; }
        g_off[NE] = s;
        int nt = 0;
        for (int e = 0; e < NE; ++e)
            for (int m = g_off[e]; m < g_off[e + 1]; m += 128) {
                g_tile_e[nt] = e; g_tile_m[nt] = m; ++nt;
            }
        for (; nt < MAXT; ++nt) g_tile_e[nt] = -1;
    }
}

// ---------------- scatter body (256 threads, runs as moe_gemm tickets 0..15) --
__device__ __forceinline__ void scatter_block(int blk, int* lcnt, int* lbase) {
    int tid = threadIdx.x;
    int tok = blk * 256 + tid;
    if (tid < NE) lcnt[tid] = 0;
    __syncthreads();
    int e0 = g_tidx[tok * 2 + 0], e1 = g_tidx[tok * 2 + 1];
    int r0 = atomicAdd(&lcnt[e0], 1);
    int r1 = atomicAdd(&lcnt[e1], 1);
    __syncthreads();
    if (tid < NE) lbase[tid] = atomicAdd(&g_cursor[tid], lcnt[tid]);
    __syncthreads();
    g_perm[g_off[e0] + lbase[e0] + r0] = tok * 2 + 0;
    g_perm[g_off[e1] + lbase[e1] + r1] = tok * 2 + 1;
}

// ---------------- GEMM tile body (R6 core, frozen) ----------------------------
#define TS 40
#define ABUF_H (128 * TS)
#define STAGE_H (2 * ABUF_H)
#define GEMM_SMEM (2 * STAGE_H * 2)   // 40960 bytes

template <int K, int NTOT, int MODE>
__device__ __forceinline__ void process_tile(
    __half* smh, float* bias_s,
    int e, int m0, int mEnd, int n0,
    const float* __restrict__ Ap, const float* __restrict__ W,
    const float* __restrict__ bias, float* __restrict__ out)
{
    const int NC = K / 32;
    int tid = threadIdx.x, lane = tid & 31, wid = tid >> 5;
    int mw = (wid >> 2) * 64;
    int nw = (wid & 3) * 32;

    if (tid < 128) bias_s[tid] = bias[e * NTOT + n0 + tid];

    int brow = tid >> 3, bc4 = tid & 7;
    const float* bP[4];
    int bOff[4];
    #pragma unroll
    for (int i = 0; i < 4; ++i) {
        int row = brow + 32 * i;
        bP[i] = W + (size_t)e * NTOT * K + (size_t)(n0 + row) * K + bc4 * 4;
        bOff[i] = row * TS + bc4 * 4;
    }

    const float* aP[4];
    const __half* aPh[2];
    int aOff[4], aOffH[2];
    if (MODE == 0) {
        #pragma unroll
        for (int i = 0; i < 4; ++i) {
            int row = brow + 32 * i;
            int gRow = m0 + row;
            int cRow = (gRow < mEnd) ? gRow : m0;
            int pair = g_perm[cRow];
            aP[i] = Ap + (size_t)(pair >> 1) * K + bc4 * 4;
            aOff[i] = row * TS + bc4 * 4;
        }
    } else {
        int arow = tid >> 2, aseg = tid & 3;
        #pragma unroll
        for (int i = 0; i < 2; ++i) {
            int row = arow + 64 * i;
            int gRow = m0 + row;
            int cRow = (gRow < mEnd) ? gRow : m0;
            aPh[i] = g_h + (size_t)cRow * K + aseg * 8;
            aOffH[i] = row * TS + aseg * 8;
        }
    }

    uint32_t sb = (uint32_t)__cvta_generic_to_shared(smh);
    uint32_t aAddrBase = sb + (uint32_t)(((mw + (lane & 15)) * TS + (lane >> 4) * 8) * 2);
    int bg = lane >> 3;
    int nblk = bg >> 1, khalf = bg & 1;
    uint32_t bAddrBase = sb + (uint32_t)((ABUF_H +
        (nw + nblk * 8 + (lane & 7)) * TS + khalf * 8) * 2);

    float acc[4][4][4];
    #pragma unroll
    for (int mi = 0; mi < 4; ++mi)
        #pragma unroll
        for (int ni = 0; ni < 4; ++ni)
            #pragma unroll
            for (int j = 0; j < 4; ++j) acc[mi][ni][j] = 0.f;

    float4 pb[4];
    float4 pa[4];
    uint4 qa[2];

    #pragma unroll
    for (int i = 0; i < 4; ++i) pb[i] = *(const float4*)(bP[i]);
    if (MODE == 0) {
        #pragma unroll
        for (int i = 0; i < 4; ++i) pa[i] = *(const float4*)(aP[i]);
    } else {
        #pragma unroll
        for (int i = 0; i < 2; ++i) qa[i] = *(const uint4*)(aPh[i]);
    }
    {
        __half* sA = smh;
        __half* sB = smh + ABUF_H;
        #pragma unroll
        for (int i = 0; i < 4; ++i) {
            uint2 u = cvt2h(pb[i]);
            *(uint2*)(sB + bOff[i]) = u;
        }
        if (MODE == 0) {
            #pragma unroll
            for (int i = 0; i < 4; ++i) {
                uint2 u = cvt2h(pa[i]);
                *(uint2*)(sA + aOff[i]) = u;
            }
        } else {
            #pragma unroll
            for (int i = 0; i < 2; ++i) *(uint4*)(sA + aOffH[i]) = qa[i];
        }
    }
    __syncthreads();

    for (int s = 0; s < NC; ++s) {
        int b = s & 1;
        if (s + 1 < NC) {
            #pragma unroll
            for (int i = 0; i < 4; ++i) pb[i] = *(const float4*)(bP[i] + (s + 1) * 32);
            if (MODE == 0) {
                #pragma unroll
                for (int i = 0; i < 4; ++i) pa[i] = *(const float4*)(aP[i] + (s + 1) * 32);
            } else {
                #pragma unroll
                for (int i = 0; i < 2; ++i) qa[i] = *(const uint4*)(aPh[i] + (s + 1) * 32);
            }
        }
        uint32_t aA = aAddrBase + (uint32_t)(b * STAGE_H * 2);
        uint32_t bA = bAddrBase + (uint32_t)(b * STAGE_H * 2);
        #pragma unroll
        for (int ks = 0; ks < 2; ++ks) {
            uint32_t af[4][4];
            #pragma unroll
            for (int mi = 0; mi < 4; ++mi)
                ldsm4(aA + mi * (16 * TS * 2) + ks * 32, af[mi]);
            uint32_t bfr[8];
            #pragma unroll
            for (int ni2 = 0; ni2 < 2; ++ni2)
                ldsm4(bA + ni2 * (16 * TS * 2) + ks * 32, &bfr[ni2 * 4]);
            #pragma unroll
            for (int mi = 0; mi < 4; ++mi)
                #pragma unroll
                for (int ni = 0; ni < 4; ++ni)
                    mma_f16(acc[mi][ni], af[mi], &bfr[ni * 2]);
        }
        if (s + 1 < NC) {
            int nb = b ^ 1;
            __half* sA = smh + nb * STAGE_H;
            __half* sB = sA + ABUF_H;
            #pragma unroll
            for (int i = 0; i < 4; ++i) {
                uint2 u = cvt2h(pb[i]);
                *(uint2*)(sB + bOff[i]) = u;
            }
            if (MODE == 0) {
                #pragma unroll
                for (int i = 0; i < 4; ++i) {
                    uint2 u = cvt2h(pa[i]);
                    *(uint2*)(sA + aOff[i]) = u;
                }
            } else {
                #pragma unroll
                for (int i = 0; i < 2; ++i) *(uint4*)(sA + aOffH[i]) = qa[i];
            }
            __syncthreads();
        }
    }

    int r4 = lane >> 2, cc = (lane & 3) * 2;
    #pragma unroll
    for (int mi = 0; mi < 4; ++mi) {
        int row0 = m0 + mw + mi * 16 + r4;
        int row1 = row0 + 8;
        bool v0 = row0 < mEnd, v1 = row1 < mEnd;
        if (MODE == 0) {
            __half* C0 = g_h + (size_t)row0 * NTOT + n0;
            __half* C1 = g_h + (size_t)row1 * NTOT + n0;
            #pragma unroll
            for (int ni = 0; ni < 4; ++ni) {
                int col = nw + ni * 8 + cc;
                float bb0 = bias_s[col], bb1 = bias_s[col + 1];
                const float* d = acc[mi][ni];
                if (v0) {
                    __half2 h = __floats2half2_rn(fmaxf(d[0] + bb0, 0.f),
                                                  fmaxf(d[1] + bb1, 0.f));
                    *(__half2*)&C0[col] = h;
                }
                if (v1) {
                    __half2 h = __floats2half2_rn(fmaxf(d[2] + bb0, 0.f),
                                                  fmaxf(d[3] + bb1, 0.f));
                    *(__half2*)&C1[col] = h;
                }
            }
        } else {
            int p0 = 0, p1 = 0;
            float w0 = 0.f, w1 = 0.f;
            if (v0) { p0 = g_perm[row0]; w0 = g_tw[p0]; }
            if (v1) { p1 = g_perm[row1]; w1 = g_tw[p1]; }
            float* O0 = out + (size_t)(p0 >> 1) * DOUT + n0;
            float* O1 = out + (size_t)(p1 >> 1) * DOUT + n0;
            #pragma unroll
            for (int ni = 0; ni < 4; ++ni) {
                int col = nw + ni * 8 + cc;
                float bb0 = bias_s[col], bb1 = bias_s[col + 1];
                const float* d = acc[mi][ni];
                if (v0) red2(O0 + col, (d[0] + bb0) * w0, (d[1] + bb1) * w0);
                if (v1) red2(O1 + col, (d[2] + bb0) * w1, (d[3] + bb1) * w1);
            }
        }
    }
}

// ---------------- persistent scatter + GEMM1 + GEMM2 --------------------------
__global__ __launch_bounds__(256, 2) void moe_gemm(const float* __restrict__ x,
                                                   const float* __restrict__ w1,
                                                   const float* __restrict__ b1,
                                                   const float* __restrict__ w2,
                                                   const float* __restrict__ b2,
                                                   float* __restrict__ out) {
    extern __shared__ __half smh[];
    __shared__ float bias_s[128];
    __shared__ int s_ctrl[2 * NE];      // scatter lcnt/lbase
    __shared__ int s_t;
    int tid = threadIdx.x;

    for (;;) {
        __syncthreads();                 // smem reuse barrier
        if (tid == 0) s_t = atomicAdd(&g_ticket, 1);
        __syncthreads();
        int t = s_t;
        if (t >= TTOT) break;

        if (t < NSCAT) {                 // scatter tickets (always first)
            scatter_block(t, s_ctrl, s_ctrl + NE);
            __threadfence();
            __syncthreads();
            if (tid == 0) atomicAdd(&g_scat, 1);
            continue;
        }
        int tt = t - NSCAT;

        if (tt < T1TOT) {
            int mt = tt / NT1, nt = tt % NT1;
            int e = g_tile_e[mt];
            if (e < 0) continue;
            if (tid == 0) {              // wait for scatter (perm) completion
                while (*(volatile int*)&g_scat < NSCAT) {}
                __threadfence();
            }
            __syncthreads();
            int m0 = g_tile_m[mt];
            int mEnd = g_off[e + 1];
            process_tile<DI, DH, 0>(smh, bias_s, e, m0, mEnd, nt * 128,
                                    x, w1, b1, nullptr);
            __threadfence();             // publish g_h stores
            __syncthreads();
            if (tid == 0) atomicAdd(&g_done[mt], 1);
        } else {
            int idx = tt - T1TOT;
            int mt = idx / NT2, nt = idx % NT2;
            int e = g_tile_e[mt];
            if (e < 0) continue;
            if (tid == 0) {
                while (*(volatile int*)&g_done[mt] < NT1) {}
                __threadfence();
            }
            __syncthreads();
            int m0 = g_tile_m[mt];
            int mEnd = g_off[e + 1];
            process_tile<DH, DOUT, 1>(smh, bias_s, e, m0, mEnd, nt * 128,
                                      nullptr, w2, b2, out);
        }
    }

    // last CTA resets control state for the next graph replay
    if (tid == 0) {
        int f = atomicAdd(&g_finish, 1);
        if (f == NCTA - 1) {
            #pragma unroll
            for (int i = 0; i < NE; ++i) { g_counts[i] = 0; g_cursor[i] = 0; }
            for (int i = 0; i < MAXT; ++i) g_done[i] = 0;
            g_ticket = 0;
            g_gatefin = 0;
            g_scat = 0;
            g_finish = 0;
            __threadfence();
        }
    }
}

// ---------------- launch -----------------------------------------------------
extern "C" void kernel_launch(void* const* d_in, const int* in_sizes, int n_in,
                              void* d_out, int out_size) {
    const float* x  = (const float*)d_in[0];
    const float* gw = (const float*)d_in[1];
    const float* w1 = (const float*)d_in[2];
    const float* b1 = (const float*)d_in[3];
    const float* w2 = (const float*)d_in[4];
    const float* b2 = (const float*)d_in[5];
    float* out = (float*)d_out;

    cudaFuncSetAttribute(moe_gemm,
                         cudaFuncAttributeMaxDynamicSharedMemorySize, GEMM_SMEM);

    gate_kernel<<<NB / GTOK + ZB, 128>>>(x, gw, out);
    moe_gemm<<<NCTA, 256, GEMM_SMEM>>>(x, w1, b1, w2, b2, out);
}

// round 15
// speedup vs baseline: 1.0787x; 1.0787x over previous
#include <cuda_runtime.h>
#include <cuda_fp16.h>
#include <math.h>
#include <stdint.h>

#define NB   4096
#define NE   16
#define DI   1024
#define DH   2048
#define DOUT 1024
#define NSLOT (NB * 2)
#define MAXT 80            // max 128-row m-tiles across experts (<=79, pad 80)
#define NT1  (DH / 128)    // 16 n-tiles in GEMM1
#define NT2  (DOUT / 128)  // 8 n-tiles in GEMM2
#define T1TOT (MAXT * NT1) // 1280
#define TTOT  (MAXT * (NT1 + NT2))
#define NCTA  296          // 2 CTAs per SM x 148 SMs
#define ZB   256           // out-zero blocks appended to gate grid
#define GTOK 8             // tokens per gate block

// ---------------- scratch ----------------------------------------------------
__device__ __half g_h[(size_t)NSLOT * DH];
__device__ int    g_perm[NSLOT];
__device__ int    g_counts[NE];
__device__ int    g_cursor[NE];
__device__ int    g_off[NE + 1];
__device__ int    g_tidx[NB * 2];
__device__ float  g_tw[NB * 2];
__device__ int    g_tile_e[MAXT];
__device__ int    g_tile_m[MAXT];
__device__ int    g_done[MAXT];
__device__ int    g_ticket;
__device__ int    g_gatefin;
__device__ int    g_finish;

// ---------------- helpers ----------------------------------------------------
__device__ __forceinline__ void ldsm4(uint32_t addr, uint32_t* a) {
    asm volatile("ldmatrix.sync.aligned.m8n8.x4.shared.b16 {%0,%1,%2,%3}, [%4];"
                 : "=r"(a[0]), "=r"(a[1]), "=r"(a[2]), "=r"(a[3]) : "r"(addr));
}
__device__ __forceinline__ void mma_f16(float* d, const uint32_t* a, const uint32_t* b) {
    asm volatile(
        "mma.sync.aligned.m16n8k16.row.col.f32.f16.f16.f32 "
        "{%0,%1,%2,%3}, {%4,%5,%6,%7}, {%8,%9}, {%0,%1,%2,%3};"
        : "+f"(d[0]), "+f"(d[1]), "+f"(d[2]), "+f"(d[3])
        : "r"(a[0]), "r"(a[1]), "r"(a[2]), "r"(a[3]), "r"(b[0]), "r"(b[1]));
}
__device__ __forceinline__ uint32_t h2bits(__half2 h) {
    return *reinterpret_cast<uint32_t*>(&h);
}
__device__ __forceinline__ uint2 cvt2h(float4 v) {
    uint2 u;
    u.x = h2bits(__floats2half2_rn(v.x, v.y));
    u.y = h2bits(__floats2half2_rn(v.z, v.w));
    return u;
}
__device__ __forceinline__ void red2(float* p, float a, float b) {
    asm volatile("red.global.add.v2.f32 [%0], {%1, %2};"
                 :: "l"(p), "f"(a), "f"(b) : "memory");
}

// ---------------- gate (fp32 exact) + co-scheduled out-zeroing ----------------
// blocks [0, NB/GTOK): gating, 8 tokens each. blocks [NB/GTOK, +ZB): zero out.
// Control state was reset by the previous moe_gemm's last CTA.
__global__ __launch_bounds__(128) void gate_kernel(const float* __restrict__ x,
                                                   const float* __restrict__ gw,
                                                   float* __restrict__ out) {
    if (blockIdx.x >= NB / GTOK) {
        int c = blockIdx.x - NB / GTOK;
        float4* o4 = (float4*)out;
        int base = c * 128 + threadIdx.x;
        const int STRIDE = ZB * 128;
        #pragma unroll 8
        for (int i = 0; i < (NB * DOUT / 4) / (ZB * 128); ++i)
            o4[base + i * STRIDE] = make_float4(0.f, 0.f, 0.f, 0.f);
        return;
    }

    __shared__ float xs[GTOK][DI];        // 32KB
    __shared__ float sc[GTOK][NE];
    __shared__ int s_last;
    int t0 = blockIdx.x * GTOK;

    const float4* xsrc = (const float4*)(x + (size_t)t0 * DI);
    float4* xd = (float4*)&xs[0][0];
    #pragma unroll 4
    for (int i = threadIdx.x; i < GTOK * DI / 4; i += 128) xd[i] = xsrc[i];
    __syncthreads();

    int warp = threadIdx.x >> 5, lane = threadIdx.x & 31;
    for (int e = warp * 4; e < warp * 4 + 4; ++e) {
        float s[GTOK];
        #pragma unroll
        for (int t = 0; t < GTOK; ++t) s[t] = 0.f;
        for (int i = lane; i < DI; i += 32) {
            float g = gw[e * DI + i];
            #pragma unroll
            for (int t = 0; t < GTOK; ++t) s[t] += xs[t][i] * g;
        }
        #pragma unroll
        for (int o = 16; o > 0; o >>= 1) {
            #pragma unroll
            for (int t = 0; t < GTOK; ++t)
                s[t] += __shfl_xor_sync(0xffffffffu, s[t], o);
        }
        if (lane == 0) {
            #pragma unroll
            for (int t = 0; t < GTOK; ++t) sc[t][e] = s[t];
        }
    }
    __syncthreads();

    if (threadIdx.x < GTOK) {
        int tt = threadIdx.x;
        int tok = t0 + tt;
        float bv = -1e30f; int bi = 0;
        #pragma unroll
        for (int e = 0; e < NE; ++e) {
            float v = sc[tt][e];
            if (v > bv) { bv = v; bi = e; }
        }
        float bv2 = -1e30f; int bi2 = 0;
        #pragma unroll
        for (int e = 0; e < NE; ++e) {
            if (e == bi) continue;
            float v = sc[tt][e];
            if (v > bv2) { bv2 = v; bi2 = e; }
        }
        float e2 = expf(bv2 - bv);
        float inv = 1.0f / (1.0f + e2);
        g_tidx[tok * 2 + 0] = bi;  g_tw[tok * 2 + 0] = inv;
        g_tidx[tok * 2 + 1] = bi2; g_tw[tok * 2 + 1] = e2 * inv;
        atomicAdd(&g_counts[bi], 1);
        atomicAdd(&g_counts[bi2], 1);
    }

    // last finished gate block computes prefix sums + tile table
    __threadfence();
    __syncthreads();
    if (threadIdx.x == 0)
        s_last = (atomicAdd(&g_gatefin, 1) == NB / GTOK - 1) ? 1 : 0;
    __syncthreads();
    if (s_last && threadIdx.x == 0) {
        int s = 0;
        #pragma unroll
        for (int e = 0; e < NE; ++e) { g_off[e] = s; s += g_counts[e]; }
        g_off[NE] = s;
        int nt = 0;
        for (int e = 0; e < NE; ++e)
            for (int m = g_off[e]; m < g_off[e + 1]; m += 128) {
                g_tile_e[nt] = e; g_tile_m[nt] = m; ++nt;
            }
        for (; nt < MAXT; ++nt) g_tile_e[nt] = -1;
    }
}

// ---------------- scatter (two-level, low contention) -------------------------
__global__ __launch_bounds__(256) void scatter_kernel() {
    __shared__ int lcnt[NE];
    __shared__ int lbase[NE];
    int tid = threadIdx.x;
    int tok = blockIdx.x * 256 + tid;
    if (tid < NE) lcnt[tid] = 0;
    __syncthreads();
    int e0 = g_tidx[tok * 2 + 0], e1 = g_tidx[tok * 2 + 1];
    int r0 = atomicAdd(&lcnt[e0], 1);
    int r1 = atomicAdd(&lcnt[e1], 1);
    __syncthreads();
    if (tid < NE) lbase[tid] = atomicAdd(&g_cursor[tid], lcnt[tid]);
    __syncthreads();
    g_perm[g_off[e0] + lbase[e0] + r0] = tok * 2 + 0;
    g_perm[g_off[e1] + lbase[e1] + r1] = tok * 2 + 1;
}

// ---------------- GEMM tile body (R6 core, frozen) ----------------------------
#define TS 40
#define ABUF_H (128 * TS)
#define STAGE_H (2 * ABUF_H)
#define GEMM_SMEM (2 * STAGE_H * 2)   // 40960 bytes

template <int K, int NTOT, int MODE>
__device__ __forceinline__ void process_tile(
    __half* smh, float* bias_s,
    int e, int m0, int mEnd, int n0,
    const float* __restrict__ Ap, const float* __restrict__ W,
    const float* __restrict__ bias, float* __restrict__ out)
{
    const int NC = K / 32;
    int tid = threadIdx.x, lane = tid & 31, wid = tid >> 5;
    int mw = (wid >> 2) * 64;
    int nw = (wid & 3) * 32;

    if (tid < 128) bias_s[tid] = bias[e * NTOT + n0 + tid];

    int brow = tid >> 3, bc4 = tid & 7;
    const float* bP[4];
    int bOff[4];
    #pragma unroll
    for (int i = 0; i < 4; ++i) {
        int row = brow + 32 * i;
        bP[i] = W + (size_t)e * NTOT * K + (size_t)(n0 + row) * K + bc4 * 4;
        bOff[i] = row * TS + bc4 * 4;
    }

    const float* aP[4];
    const __half* aPh[2];
    int aOff[4], aOffH[2];
    if (MODE == 0) {
        #pragma unroll
        for (int i = 0; i < 4; ++i) {
            int row = brow + 32 * i;
            int gRow = m0 + row;
            int cRow = (gRow < mEnd) ? gRow : m0;
            int pair = g_perm[cRow];
            aP[i] = Ap + (size_t)(pair >> 1) * K + bc4 * 4;
            aOff[i] = row * TS + bc4 * 4;
        }
    } else {
        int arow = tid >> 2, aseg = tid & 3;
        #pragma unroll
        for (int i = 0; i < 2; ++i) {
            int row = arow + 64 * i;
            int gRow = m0 + row;
            int cRow = (gRow < mEnd) ? gRow : m0;
            aPh[i] = g_h + (size_t)cRow * K + aseg * 8;
            aOffH[i] = row * TS + aseg * 8;
        }
    }

    uint32_t sb = (uint32_t)__cvta_generic_to_shared(smh);
    uint32_t aAddrBase = sb + (uint32_t)(((mw + (lane & 15)) * TS + (lane >> 4) * 8) * 2);
    int bg = lane >> 3;
    int nblk = bg >> 1, khalf = bg & 1;
    uint32_t bAddrBase = sb + (uint32_t)((ABUF_H +
        (nw + nblk * 8 + (lane & 7)) * TS + khalf * 8) * 2);

    float acc[4][4][4];
    #pragma unroll
    for (int mi = 0; mi < 4; ++mi)
        #pragma unroll
        for (int ni = 0; ni < 4; ++ni)
            #pragma unroll
            for (int j = 0; j < 4; ++j) acc[mi][ni][j] = 0.f;

    float4 pb[4];
    float4 pa[4];
    uint4 qa[2];

    #pragma unroll
    for (int i = 0; i < 4; ++i) pb[i] = *(const float4*)(bP[i]);
    if (MODE == 0) {
        #pragma unroll
        for (int i = 0; i < 4; ++i) pa[i] = *(const float4*)(aP[i]);
    } else {
        #pragma unroll
        for (int i = 0; i < 2; ++i) qa[i] = *(const uint4*)(aPh[i]);
    }
    {
        __half* sA = smh;
        __half* sB = smh + ABUF_H;
        #pragma unroll
        for (int i = 0; i < 4; ++i) {
            uint2 u = cvt2h(pb[i]);
            *(uint2*)(sB + bOff[i]) = u;
        }
        if (MODE == 0) {
            #pragma unroll
            for (int i = 0; i < 4; ++i) {
                uint2 u = cvt2h(pa[i]);
                *(uint2*)(sA + aOff[i]) = u;
            }
        } else {
            #pragma unroll
            for (int i = 0; i < 2; ++i) *(uint4*)(sA + aOffH[i]) = qa[i];
        }
    }
    __syncthreads();

    for (int s = 0; s < NC; ++s) {
        int b = s & 1;
        if (s + 1 < NC) {
            #pragma unroll
            for (int i = 0; i < 4; ++i) pb[i] = *(const float4*)(bP[i] + (s + 1) * 32);
            if (MODE == 0) {
                #pragma unroll
                for (int i = 0; i < 4; ++i) pa[i] = *(const float4*)(aP[i] + (s + 1) * 32);
            } else {
                #pragma unroll
                for (int i = 0; i < 2; ++i) qa[i] = *(const uint4*)(aPh[i] + (s + 1) * 32);
            }
        }
        uint32_t aA = aAddrBase + (uint32_t)(b * STAGE_H * 2);
        uint32_t bA = bAddrBase + (uint32_t)(b * STAGE_H * 2);
        #pragma unroll
        for (int ks = 0; ks < 2; ++ks) {
            uint32_t af[4][4];
            #pragma unroll
            for (int mi = 0; mi < 4; ++mi)
                ldsm4(aA + mi * (16 * TS * 2) + ks * 32, af[mi]);
            uint32_t bfr[8];
            #pragma unroll
            for (int ni2 = 0; ni2 < 2; ++ni2)
                ldsm4(bA + ni2 * (16 * TS * 2) + ks * 32, &bfr[ni2 * 4]);
            #pragma unroll
            for (int mi = 0; mi < 4; ++mi)
                #pragma unroll
                for (int ni = 0; ni < 4; ++ni)
                    mma_f16(acc[mi][ni], af[mi], &bfr[ni * 2]);
        }
        if (s + 1 < NC) {
            int nb = b ^ 1;
            __half* sA = smh + nb * STAGE_H;
            __half* sB = sA + ABUF_H;
            #pragma unroll
            for (int i = 0; i < 4; ++i) {
                uint2 u = cvt2h(pb[i]);
                *(uint2*)(sB + bOff[i]) = u;
            }
            if (MODE == 0) {
                #pragma unroll
                for (int i = 0; i < 4; ++i) {
                    uint2 u = cvt2h(pa[i]);
                    *(uint2*)(sA + aOff[i]) = u;
                }
            } else {
                #pragma unroll
                for (int i = 0; i < 2; ++i) *(uint4*)(sA + aOffH[i]) = qa[i];
            }
            __syncthreads();
        }
    }

    int r4 = lane >> 2, cc = (lane & 3) * 2;
    #pragma unroll
    for (int mi = 0; mi < 4; ++mi) {
        int row0 = m0 + mw + mi * 16 + r4;
        int row1 = row0 + 8;
        bool v0 = row0 < mEnd, v1 = row1 < mEnd;
        if (MODE == 0) {
            __half* C0 = g_h + (size_t)row0 * NTOT + n0;
            __half* C1 = g_h + (size_t)row1 * NTOT + n0;
            #pragma unroll
            for (int ni = 0; ni < 4; ++ni) {
                int col = nw + ni * 8 + cc;
                float bb0 = bias_s[col], bb1 = bias_s[col + 1];
                const float* d = acc[mi][ni];
                if (v0) {
                    __half2 h = __floats2half2_rn(fmaxf(d[0] + bb0, 0.f),
                                                  fmaxf(d[1] + bb1, 0.f));
                    *(__half2*)&C0[col] = h;
                }
                if (v1) {
                    __half2 h = __floats2half2_rn(fmaxf(d[2] + bb0, 0.f),
                                                  fmaxf(d[3] + bb1, 0.f));
                    *(__half2*)&C1[col] = h;
                }
            }
        } else {
            int p0 = 0, p1 = 0;
            float w0 = 0.f, w1 = 0.f;
            if (v0) { p0 = g_perm[row0]; w0 = g_tw[p0]; }
            if (v1) { p1 = g_perm[row1]; w1 = g_tw[p1]; }
            float* O0 = out + (size_t)(p0 >> 1) * DOUT + n0;
            float* O1 = out + (size_t)(p1 >> 1) * DOUT + n0;
            #pragma unroll
            for (int ni = 0; ni < 4; ++ni) {
                int col = nw + ni * 8 + cc;
                float bb0 = bias_s[col], bb1 = bias_s[col + 1];
                const float* d = acc[mi][ni];
                if (v0) red2(O0 + col, (d[0] + bb0) * w0, (d[1] + bb1) * w0);
                if (v1) red2(O1 + col, (d[2] + bb0) * w1, (d[3] + bb1) * w1);
            }
        }
    }
}

// ---------------- persistent fused GEMM1+GEMM2 (R13 ticket loop) --------------
__global__ __launch_bounds__(256, 2) void moe_gemm(const float* __restrict__ x,
                                                   const float* __restrict__ w1,
                                                   const float* __restrict__ b1,
                                                   const float* __restrict__ w2,
                                                   const float* __restrict__ b2,
                                                   float* __restrict__ out) {
    extern __shared__ __half smh[];
    __shared__ float bias_s[128];
    __shared__ int s_t;
    int tid = threadIdx.x;

    for (;;) {
        __syncthreads();                 // smem/bias_s reuse barrier
        if (tid == 0) s_t = atomicAdd(&g_ticket, 1);
        __syncthreads();
        int t = s_t;
        if (t >= TTOT) break;

        if (t < T1TOT) {
            int mt = t / NT1, nt = t % NT1;
            int e = g_tile_e[mt];
            if (e < 0) continue;
            int m0 = g_tile_m[mt];
            int mEnd = g_off[e + 1];
            process_tile<DI, DH, 0>(smh, bias_s, e, m0, mEnd, nt * 128,
                                    x, w1, b1, nullptr);
            __threadfence();             // publish g_h stores
            __syncthreads();
            if (tid == 0) atomicAdd(&g_done[mt], 1);
        } else {
            int idx = t - T1TOT;
            int mt = idx / NT2, nt = idx % NT2;
            int e = g_tile_e[mt];
            if (e < 0) continue;
            if (tid == 0) {
                while (*(volatile int*)&g_done[mt] < NT1) {}
                __threadfence();
            }
            __syncthreads();
            int m0 = g_tile_m[mt];
            int mEnd = g_off[e + 1];
            process_tile<DH, DOUT, 1>(smh, bias_s, e, m0, mEnd, nt * 128,
                                      nullptr, w2, b2, out);
        }
    }

    // last CTA resets control state for the next graph replay
    if (tid == 0) {
        int f = atomicAdd(&g_finish, 1);
        if (f == NCTA - 1) {
            #pragma unroll
            for (int i = 0; i < NE; ++i) { g_counts[i] = 0; g_cursor[i] = 0; }
            for (int i = 0; i < MAXT; ++i) g_done[i] = 0;
            g_ticket = 0;
            g_gatefin = 0;
            g_finish = 0;
            __threadfence();
        }
    }
}

// ---------------- launch -----------------------------------------------------
extern "C" void kernel_launch(void* const* d_in, const int* in_sizes, int n_in,
                              void* d_out, int out_size) {
    const float* x  = (const float*)d_in[0];
    const float* gw = (const float*)d_in[1];
    const float* w1 = (const float*)d_in[2];
    const float* b1 = (const float*)d_in[3];
    const float* w2 = (const float*)d_in[4];
    const float* b2 = (const float*)d_in[5];
    float* out = (float*)d_out;

    cudaFuncSetAttribute(moe_gemm,
                         cudaFuncAttributeMaxDynamicSharedMemorySize, GEMM_SMEM);

    gate_kernel<<<NB / GTOK + ZB, 128>>>(x, gw, out);
    scatter_kernel<<<NB / 256, 256>>>();
    moe_gemm<<<NCTA, 256, GEMM_SMEM>>>(x, w1, b1, w2, b2, out);
}

// round 16
// speedup vs baseline: 1.0823x; 1.0034x over previous
#include <cuda_runtime.h>
#include <cuda_fp16.h>
#include <math.h>
#include <stdint.h>

#define NB   4096
#define NE   16
#define DI   1024
#define DH   2048
#define DOUT 1024
#define NSLOT (NB * 2)
#define MAXT 80            // max 128-row m-tiles across experts (<=79, pad 80)
#define NT1  (DH / 128)    // 16 n-tiles in GEMM1
#define NT2  (DOUT / 128)  // 8 n-tiles in GEMM2
#define T1TOT (MAXT * NT1) // 1280
#define TTOT  (MAXT * (NT1 + NT2))
#define NCTA  296          // 2 CTAs per SM x 148 SMs
#define ZB   256           // out-zero blocks appended to gate grid
#define GTOK 4             // tokens per gate block (16KB smem -> high occ)

// ---------------- scratch ----------------------------------------------------
__device__ __half g_h[(size_t)NSLOT * DH];
__device__ int    g_perm[NSLOT];
__device__ int    g_counts[NE];
__device__ int    g_cursor[NE];
__device__ int    g_off[NE + 1];
__device__ int    g_tidx[NB * 2];
__device__ float  g_tw[NB * 2];
__device__ int    g_tile_e[MAXT];
__device__ int    g_tile_m[MAXT];
__device__ int    g_done[MAXT];
__device__ int    g_ticket;
__device__ int    g_gatefin;
__device__ int    g_finish;

// ---------------- helpers ----------------------------------------------------
__device__ __forceinline__ void ldsm4(uint32_t addr, uint32_t* a) {
    asm volatile("ldmatrix.sync.aligned.m8n8.x4.shared.b16 {%0,%1,%2,%3}, [%4];"
                 : "=r"(a[0]), "=r"(a[1]), "=r"(a[2]), "=r"(a[3]) : "r"(addr));
}
__device__ __forceinline__ void mma_f16(float* d, const uint32_t* a, const uint32_t* b) {
    asm volatile(
        "mma.sync.aligned.m16n8k16.row.col.f32.f16.f16.f32 "
        "{%0,%1,%2,%3}, {%4,%5,%6,%7}, {%8,%9}, {%0,%1,%2,%3};"
        : "+f"(d[0]), "+f"(d[1]), "+f"(d[2]), "+f"(d[3])
        : "r"(a[0]), "r"(a[1]), "r"(a[2]), "r"(a[3]), "r"(b[0]), "r"(b[1]));
}
__device__ __forceinline__ uint32_t h2bits(__half2 h) {
    return *reinterpret_cast<uint32_t*>(&h);
}
__device__ __forceinline__ uint2 cvt2h(float4 v) {
    uint2 u;
    u.x = h2bits(__floats2half2_rn(v.x, v.y));
    u.y = h2bits(__floats2half2_rn(v.z, v.w));
    return u;
}
__device__ __forceinline__ void red2(float* p, float a, float b) {
    asm volatile("red.global.add.v2.f32 [%0], {%1, %2};"
                 :: "l"(p), "f"(a), "f"(b) : "memory");
}
__device__ __forceinline__ float dot4(float4 a, float4 b, float acc) {
    acc = fmaf(a.x, b.x, acc);
    acc = fmaf(a.y, b.y, acc);
    acc = fmaf(a.z, b.z, acc);
    acc = fmaf(a.w, b.w, acc);
    return acc;
}

// ---------------- gate (fp32, float4 inner loop) + co-scheduled zeroing -------
// blocks [0, NB/GTOK): gating. blocks [NB/GTOK, +ZB): zero out (16MB).
// Control state was reset by the previous moe_gemm's last CTA.
__global__ __launch_bounds__(128) void gate_kernel(const float* __restrict__ x,
                                                   const float* __restrict__ gw,
                                                   float* __restrict__ out) {
    if (blockIdx.x >= NB / GTOK) {
        int c = blockIdx.x - NB / GTOK;
        float4* o4 = (float4*)out;
        int base = c * 128 + threadIdx.x;
        const int STRIDE = ZB * 128;
        #pragma unroll 8
        for (int i = 0; i < (NB * DOUT / 4) / (ZB * 128); ++i)
            o4[base + i * STRIDE] = make_float4(0.f, 0.f, 0.f, 0.f);
        return;
    }

    __shared__ float xs[GTOK][DI];        // 16KB
    __shared__ float sc[GTOK][NE];
    __shared__ int s_last;
    int t0 = blockIdx.x * GTOK;

    const float4* xsrc = (const float4*)(x + (size_t)t0 * DI);
    float4* xd = (float4*)&xs[0][0];
    #pragma unroll 4
    for (int i = threadIdx.x; i < GTOK * DI / 4; i += 128) xd[i] = xsrc[i];
    __syncthreads();

    int warp = threadIdx.x >> 5, lane = threadIdx.x & 31;
    const float4* x40 = (const float4*)&xs[0][0];
    const float4* x41 = (const float4*)&xs[1][0];
    const float4* x42 = (const float4*)&xs[2][0];
    const float4* x43 = (const float4*)&xs[3][0];
    for (int e = warp * 4; e < warp * 4 + 4; ++e) {
        const float4* g4 = (const float4*)(gw + (size_t)e * DI);
        float s0 = 0.f, s1 = 0.f, s2 = 0.f, s3 = 0.f;
        #pragma unroll
        for (int i = lane; i < DI / 4; i += 32) {
            float4 g = g4[i];
            s0 = dot4(x40[i], g, s0);
            s1 = dot4(x41[i], g, s1);
            s2 = dot4(x42[i], g, s2);
            s3 = dot4(x43[i], g, s3);
        }
        #pragma unroll
        for (int o = 16; o > 0; o >>= 1) {
            s0 += __shfl_xor_sync(0xffffffffu, s0, o);
            s1 += __shfl_xor_sync(0xffffffffu, s1, o);
            s2 += __shfl_xor_sync(0xffffffffu, s2, o);
            s3 += __shfl_xor_sync(0xffffffffu, s3, o);
        }
        if (lane == 0) { sc[0][e] = s0; sc[1][e] = s1; sc[2][e] = s2; sc[3][e] = s3; }
    }
    __syncthreads();

    if (threadIdx.x < GTOK) {
        int tt = threadIdx.x;
        int tok = t0 + tt;
        float bv = -1e30f; int bi = 0;
        #pragma unroll
        for (int e = 0; e < NE; ++e) {
            float v = sc[tt][e];
            if (v > bv) { bv = v; bi = e; }
        }
        float bv2 = -1e30f; int bi2 = 0;
        #pragma unroll
        for (int e = 0; e < NE; ++e) {
            if (e == bi) continue;
            float v = sc[tt][e];
            if (v > bv2) { bv2 = v; bi2 = e; }
        }
        float e2 = expf(bv2 - bv);
        float inv = 1.0f / (1.0f + e2);
        g_tidx[tok * 2 + 0] = bi;  g_tw[tok * 2 + 0] = inv;
        g_tidx[tok * 2 + 1] = bi2; g_tw[tok * 2 + 1] = e2 * inv;
        atomicAdd(&g_counts[bi], 1);
        atomicAdd(&g_counts[bi2], 1);
    }

    // last finished gate block computes prefix sums + tile table
    __threadfence();
    __syncthreads();
    if (threadIdx.x == 0)
        s_last = (atomicAdd(&g_gatefin, 1) == NB / GTOK - 1) ? 1 : 0;
    __syncthreads();
    if (s_last && threadIdx.x == 0) {
        int s = 0;
        #pragma unroll
        for (int e = 0; e < NE; ++e) { g_off[e] = s; s += g_counts[e]; }
        g_off[NE] = s;
        int nt = 0;
        for (int e = 0; e < NE; ++e)
            for (int m = g_off[e]; m < g_off[e + 1]; m += 128) {
                g_tile_e[nt] = e; g_tile_m[nt] = m; ++nt;
            }
        for (; nt < MAXT; ++nt) g_tile_e[nt] = -1;
    }
}

// ---------------- scatter (two-level, low contention) -------------------------
__global__ __launch_bounds__(256) void scatter_kernel() {
    __shared__ int lcnt[NE];
    __shared__ int lbase[NE];
    int tid = threadIdx.x;
    int tok = blockIdx.x * 256 + tid;
    if (tid < NE) lcnt[tid] = 0;
    __syncthreads();
    int e0 = g_tidx[tok * 2 + 0], e1 = g_tidx[tok * 2 + 1];
    int r0 = atomicAdd(&lcnt[e0], 1);
    int r1 = atomicAdd(&lcnt[e1], 1);
    __syncthreads();
    if (tid < NE) lbase[tid] = atomicAdd(&g_cursor[tid], lcnt[tid]);
    __syncthreads();
    g_perm[g_off[e0] + lbase[e0] + r0] = tok * 2 + 0;
    g_perm[g_off[e1] + lbase[e1] + r1] = tok * 2 + 1;
}

// ---------------- GEMM tile body (R6 core, frozen) ----------------------------
#define TS 40
#define ABUF_H (128 * TS)
#define STAGE_H (2 * ABUF_H)
#define GEMM_SMEM (2 * STAGE_H * 2)   // 40960 bytes

template <int K, int NTOT, int MODE>
__device__ __forceinline__ void process_tile(
    __half* smh, float* bias_s,
    int e, int m0, int mEnd, int n0,
    const float* __restrict__ Ap, const float* __restrict__ W,
    const float* __restrict__ bias, float* __restrict__ out)
{
    const int NC = K / 32;
    int tid = threadIdx.x, lane = tid & 31, wid = tid >> 5;
    int mw = (wid >> 2) * 64;
    int nw = (wid & 3) * 32;

    if (tid < 128) bias_s[tid] = bias[e * NTOT + n0 + tid];

    int brow = tid >> 3, bc4 = tid & 7;
    const float* bP[4];
    int bOff[4];
    #pragma unroll
    for (int i = 0; i < 4; ++i) {
        int row = brow + 32 * i;
        bP[i] = W + (size_t)e * NTOT * K + (size_t)(n0 + row) * K + bc4 * 4;
        bOff[i] = row * TS + bc4 * 4;
    }

    const float* aP[4];
    const __half* aPh[2];
    int aOff[4], aOffH[2];
    if (MODE == 0) {
        #pragma unroll
        for (int i = 0; i < 4; ++i) {
            int row = brow + 32 * i;
            int gRow = m0 + row;
            int cRow = (gRow < mEnd) ? gRow : m0;
            int pair = g_perm[cRow];
            aP[i] = Ap + (size_t)(pair >> 1) * K + bc4 * 4;
            aOff[i] = row * TS + bc4 * 4;
        }
    } else {
        int arow = tid >> 2, aseg = tid & 3;
        #pragma unroll
        for (int i = 0; i < 2; ++i) {
            int row = arow + 64 * i;
            int gRow = m0 + row;
            int cRow = (gRow < mEnd) ? gRow : m0;
            aPh[i] = g_h + (size_t)cRow * K + aseg * 8;
            aOffH[i] = row * TS + aseg * 8;
        }
    }

    uint32_t sb = (uint32_t)__cvta_generic_to_shared(smh);
    uint32_t aAddrBase = sb + (uint32_t)(((mw + (lane & 15)) * TS + (lane >> 4) * 8) * 2);
    int bg = lane >> 3;
    int nblk = bg >> 1, khalf = bg & 1;
    uint32_t bAddrBase = sb + (uint32_t)((ABUF_H +
        (nw + nblk * 8 + (lane & 7)) * TS + khalf * 8) * 2);

    float acc[4][4][4];
    #pragma unroll
    for (int mi = 0; mi < 4; ++mi)
        #pragma unroll
        for (int ni = 0; ni < 4; ++ni)
            #pragma unroll
            for (int j = 0; j < 4; ++j) acc[mi][ni][j] = 0.f;

    float4 pb[4];
    float4 pa[4];
    uint4 qa[2];

    #pragma unroll
    for (int i = 0; i < 4; ++i) pb[i] = *(const float4*)(bP[i]);
    if (MODE == 0) {
        #pragma unroll
        for (int i = 0; i < 4; ++i) pa[i] = *(const float4*)(aP[i]);
    } else {
        #pragma unroll
        for (int i = 0; i < 2; ++i) qa[i] = *(const uint4*)(aPh[i]);
    }
    {
        __half* sA = smh;
        __half* sB = smh + ABUF_H;
        #pragma unroll
        for (int i = 0; i < 4; ++i) {
            uint2 u = cvt2h(pb[i]);
            *(uint2*)(sB + bOff[i]) = u;
        }
        if (MODE == 0) {
            #pragma unroll
            for (int i = 0; i < 4; ++i) {
                uint2 u = cvt2h(pa[i]);
                *(uint2*)(sA + aOff[i]) = u;
            }
        } else {
            #pragma unroll
            for (int i = 0; i < 2; ++i) *(uint4*)(sA + aOffH[i]) = qa[i];
        }
    }
    __syncthreads();

    for (int s = 0; s < NC; ++s) {
        int b = s & 1;
        if (s + 1 < NC) {
            #pragma unroll
            for (int i = 0; i < 4; ++i) pb[i] = *(const float4*)(bP[i] + (s + 1) * 32);
            if (MODE == 0) {
                #pragma unroll
                for (int i = 0; i < 4; ++i) pa[i] = *(const float4*)(aP[i] + (s + 1) * 32);
            } else {
                #pragma unroll
                for (int i = 0; i < 2; ++i) qa[i] = *(const uint4*)(aPh[i] + (s + 1) * 32);
            }
        }
        uint32_t aA = aAddrBase + (uint32_t)(b * STAGE_H * 2);
        uint32_t bA = bAddrBase + (uint32_t)(b * STAGE_H * 2);
        #pragma unroll
        for (int ks = 0; ks < 2; ++ks) {
            uint32_t af[4][4];
            #pragma unroll
            for (int mi = 0; mi < 4; ++mi)
                ldsm4(aA + mi * (16 * TS * 2) + ks * 32, af[mi]);
            uint32_t bfr[8];
            #pragma unroll
            for (int ni2 = 0; ni2 < 2; ++ni2)
                ldsm4(bA + ni2 * (16 * TS * 2) + ks * 32, &bfr[ni2 * 4]);
            #pragma unroll
            for (int mi = 0; mi < 4; ++mi)
                #pragma unroll
                for (int ni = 0; ni < 4; ++ni)
                    mma_f16(acc[mi][ni], af[mi], &bfr[ni * 2]);
        }
        if (s + 1 < NC) {
            int nb = b ^ 1;
            __half* sA = smh + nb * STAGE_H;
            __half* sB = sA + ABUF_H;
            #pragma unroll
            for (int i = 0; i < 4; ++i) {
                uint2 u = cvt2h(pb[i]);
                *(uint2*)(sB + bOff[i]) = u;
            }
            if (MODE == 0) {
                #pragma unroll
                for (int i = 0; i < 4; ++i) {
                    uint2 u = cvt2h(pa[i]);
                    *(uint2*)(sA + aOff[i]) = u;
                }
            } else {
                #pragma unroll
                for (int i = 0; i < 2; ++i) *(uint4*)(sA + aOffH[i]) = qa[i];
            }
            __syncthreads();
        }
    }

    int r4 = lane >> 2, cc = (lane & 3) * 2;
    #pragma unroll
    for (int mi = 0; mi < 4; ++mi) {
        int row0 = m0 + mw + mi * 16 + r4;
        int row1 = row0 + 8;
        bool v0 = row0 < mEnd, v1 = row1 < mEnd;
        if (MODE == 0) {
            __half* C0 = g_h + (size_t)row0 * NTOT + n0;
            __half* C1 = g_h + (size_t)row1 * NTOT + n0;
            #pragma unroll
            for (int ni = 0; ni < 4; ++ni) {
                int col = nw + ni * 8 + cc;
                float bb0 = bias_s[col], bb1 = bias_s[col + 1];
                const float* d = acc[mi][ni];
                if (v0) {
                    __half2 h = __floats2half2_rn(fmaxf(d[0] + bb0, 0.f),
                                                  fmaxf(d[1] + bb1, 0.f));
                    *(__half2*)&C0[col] = h;
                }
                if (v1) {
                    __half2 h = __floats2half2_rn(fmaxf(d[2] + bb0, 0.f),
                                                  fmaxf(d[3] + bb1, 0.f));
                    *(__half2*)&C1[col] = h;
                }
            }
        } else {
            int p0 = 0, p1 = 0;
            float w0 = 0.f, w1 = 0.f;
            if (v0) { p0 = g_perm[row0]; w0 = g_tw[p0]; }
            if (v1) { p1 = g_perm[row1]; w1 = g_tw[p1]; }
            float* O0 = out + (size_t)(p0 >> 1) * DOUT + n0;
            float* O1 = out + (size_t)(p1 >> 1) * DOUT + n0;
            #pragma unroll
            for (int ni = 0; ni < 4; ++ni) {
                int col = nw + ni * 8 + cc;
                float bb0 = bias_s[col], bb1 = bias_s[col + 1];
                const float* d = acc[mi][ni];
                if (v0) red2(O0 + col, (d[0] + bb0) * w0, (d[1] + bb1) * w0);
                if (v1) red2(O1 + col, (d[2] + bb0) * w1, (d[3] + bb1) * w1);
            }
        }
    }
}

// ---------------- persistent fused GEMM1+GEMM2 (R13 ticket loop) --------------
__global__ __launch_bounds__(256, 2) void moe_gemm(const float* __restrict__ x,
                                                   const float* __restrict__ w1,
                                                   const float* __restrict__ b1,
                                                   const float* __restrict__ w2,
                                                   const float* __restrict__ b2,
                                                   float* __restrict__ out) {
    extern __shared__ __half smh[];
    __shared__ float bias_s[128];
    __shared__ int s_t;
    int tid = threadIdx.x;

    for (;;) {
        __syncthreads();                 // smem/bias_s reuse barrier
        if (tid == 0) s_t = atomicAdd(&g_ticket, 1);
        __syncthreads();
        int t = s_t;
        if (t >= TTOT) break;

        if (t < T1TOT) {
            int mt = t / NT1, nt = t % NT1;
            int e = g_tile_e[mt];
            if (e < 0) continue;
            int m0 = g_tile_m[mt];
            int mEnd = g_off[e + 1];
            process_tile<DI, DH, 0>(smh, bias_s, e, m0, mEnd, nt * 128,
                                    x, w1, b1, nullptr);
            __threadfence();             // publish g_h stores
            __syncthreads();
            if (tid == 0) atomicAdd(&g_done[mt], 1);
        } else {
            int idx = t - T1TOT;
            int mt = idx / NT2, nt = idx % NT2;
            int e = g_tile_e[mt];
            if (e < 0) continue;
            if (tid == 0) {
                while (*(volatile int*)&g_done[mt] < NT1) {}
                __threadfence();
            }
            __syncthreads();
            int m0 = g_tile_m[mt];
            int mEnd = g_off[e + 1];
            process_tile<DH, DOUT, 1>(smh, bias_s, e, m0, mEnd, nt * 128,
                                      nullptr, w2, b2, out);
        }
    }

    // last CTA resets control state for the next graph replay
    if (tid == 0) {
        int f = atomicAdd(&g_finish, 1);
        if (f == NCTA - 1) {
            #pragma unroll
            for (int i = 0; i < NE; ++i) { g_counts[i] = 0; g_cursor[i] = 0; }
            for (int i = 0; i < MAXT; ++i) g_done[i] = 0;
            g_ticket = 0;
            g_gatefin = 0;
            g_finish = 0;
            __threadfence();
        }
    }
}

// ---------------- launch -----------------------------------------------------
extern "C" void kernel_launch(void* const* d_in, const int* in_sizes, int n_in,
                              void* d_out, int out_size) {
    const float* x  = (const float*)d_in[0];
    const float* gw = (const float*)d_in[1];
    const float* w1 = (const float*)d_in[2];
    const float* b1 = (const float*)d_in[3];
    const float* w2 = (const float*)d_in[4];
    const float* b2 = (const float*)d_in[5];
    float* out = (float*)d_out;

    cudaFuncSetAttribute(moe_gemm,
                         cudaFuncAttributeMaxDynamicSharedMemorySize, GEMM_SMEM);

    gate_kernel<<<NB / GTOK + ZB, 128>>>(x, gw, out);
    scatter_kernel<<<NB / 256, 256>>>();
    moe_gemm<<<NCTA, 256, GEMM_SMEM>>>(x, w1, b1, w2, b2, out);
}

// round 17
// speedup vs baseline: 1.1056x; 1.0215x over previous
#include <cuda_runtime.h>
#include <cuda_fp16.h>
#include <math.h>
#include <stdint.h>

#define NB   4096
#define NE   16
#define DI   1024
#define DH   2048
#define DOUT 1024
#define NSLOT (NB * 2)
#define MAXT 80            // max 128-row m-tiles across experts (<=79, pad 80)
#define NT1  (DH / 128)    // 16 n-tiles in GEMM1
#define NT2  (DOUT / 128)  // 8 n-tiles in GEMM2
#define T1TOT (MAXT * NT1) // 1280
#define TTOT  (MAXT * (NT1 + NT2))
#define NCTA  296          // 2 CTAs per SM x 148 SMs
#define ZB   256           // out-zero blocks appended to gate grid
#define GBLK 128           // gate compute blocks (32 tokens each)
#define GATE_SMEM (NE * DI * 4)   // 64KB: full gw in smem

// ---------------- scratch ----------------------------------------------------
__device__ __half g_h[(size_t)NSLOT * DH];
__device__ int    g_perm[NSLOT];
__device__ int    g_counts[NE];
__device__ int    g_cursor[NE];
__device__ int    g_off[NE + 1];
__device__ int    g_tidx[NB * 2];
__device__ float  g_tw[NB * 2];
__device__ int    g_tile_e[MAXT];
__device__ int    g_tile_m[MAXT];
__device__ int    g_done[MAXT];
__device__ int    g_ticket;
__device__ int    g_gatefin;
__device__ int    g_finish;

// ---------------- helpers ----------------------------------------------------
__device__ __forceinline__ void ldsm4(uint32_t addr, uint32_t* a) {
    asm volatile("ldmatrix.sync.aligned.m8n8.x4.shared.b16 {%0,%1,%2,%3}, [%4];"
                 : "=r"(a[0]), "=r"(a[1]), "=r"(a[2]), "=r"(a[3]) : "r"(addr));
}
__device__ __forceinline__ void mma_f16(float* d, const uint32_t* a, const uint32_t* b) {
    asm volatile(
        "mma.sync.aligned.m16n8k16.row.col.f32.f16.f16.f32 "
        "{%0,%1,%2,%3}, {%4,%5,%6,%7}, {%8,%9}, {%0,%1,%2,%3};"
        : "+f"(d[0]), "+f"(d[1]), "+f"(d[2]), "+f"(d[3])
        : "r"(a[0]), "r"(a[1]), "r"(a[2]), "r"(a[3]), "r"(b[0]), "r"(b[1]));
}
__device__ __forceinline__ uint32_t h2bits(__half2 h) {
    return *reinterpret_cast<uint32_t*>(&h);
}
__device__ __forceinline__ uint2 cvt2h(float4 v) {
    uint2 u;
    u.x = h2bits(__floats2half2_rn(v.x, v.y));
    u.y = h2bits(__floats2half2_rn(v.z, v.w));
    return u;
}
__device__ __forceinline__ void red2(float* p, float a, float b) {
    asm volatile("red.global.add.v2.f32 [%0], {%1, %2};"
                 :: "l"(p), "f"(a), "f"(b) : "memory");
}
__device__ __forceinline__ float dot4(float4 a, float4 b, float acc) {
    acc = fmaf(a.x, b.x, acc);
    acc = fmaf(a.y, b.y, acc);
    acc = fmaf(a.z, b.z, acc);
    acc = fmaf(a.w, b.w, acc);
    return acc;
}

// ---------------- gate: gw in smem, x in regs, warp-per-token -----------------
// blocks [0, GBLK): gating (32 tokens each). blocks [GBLK, GBLK+ZB): zero out.
// Control state was reset by the previous moe_gemm's last CTA.
__global__ __launch_bounds__(256) void gate_kernel(const float* __restrict__ x,
                                                   const float* __restrict__ gw,
                                                   float* __restrict__ out) {
    if (blockIdx.x >= GBLK) {
        int c = blockIdx.x - GBLK;
        float4* o4 = (float4*)out;
        int base = c * 256 + threadIdx.x;
        const int STRIDE = ZB * 256;
        #pragma unroll 4
        for (int i = 0; i < (NB * DOUT / 4) / (ZB * 256); ++i)
            o4[base + i * STRIDE] = make_float4(0.f, 0.f, 0.f, 0.f);
        return;
    }

    extern __shared__ float sgw[];          // 64KB: gw[NE][DI]
    __shared__ float sc[32][NE];
    __shared__ int s_last;
    int tid = threadIdx.x, warp = tid >> 5, lane = tid & 31;

    // cooperative load of full gw into smem
    {
        float4* d = (float4*)sgw;
        const float4* s = (const float4*)gw;
        #pragma unroll
        for (int i = tid; i < NE * DI / 4; i += 256) d[i] = s[i];
    }
    __syncthreads();

    #pragma unroll
    for (int r = 0; r < 4; ++r) {
        int tl = warp * 4 + r;              // local token 0..31
        int tok = blockIdx.x * 32 + tl;
        float4 xr[8];
        const float4* x4 = (const float4*)(x + (size_t)tok * DI);
        #pragma unroll
        for (int j = 0; j < 8; ++j) xr[j] = x4[lane + 32 * j];
        #pragma unroll
        for (int e = 0; e < NE; ++e) {
            const float4* g4 = (const float4*)(sgw + e * DI);
            float s = 0.f;
            #pragma unroll
            for (int j = 0; j < 8; ++j) s = dot4(xr[j], g4[lane + 32 * j], s);
            #pragma unroll
            for (int o = 16; o > 0; o >>= 1) s += __shfl_xor_sync(0xffffffffu, s, o);
            if (lane == 0) sc[tl][e] = s;
        }
    }
    __syncthreads();

    if (tid < 32) {
        int tok = blockIdx.x * 32 + tid;
        float bv = -1e30f; int bi = 0;
        #pragma unroll
        for (int e = 0; e < NE; ++e) {
            float v = sc[tid][e];
            if (v > bv) { bv = v; bi = e; }
        }
        float bv2 = -1e30f; int bi2 = 0;
        #pragma unroll
        for (int e = 0; e < NE; ++e) {
            if (e == bi) continue;
            float v = sc[tid][e];
            if (v > bv2) { bv2 = v; bi2 = e; }
        }
        float e2 = expf(bv2 - bv);
        float inv = 1.0f / (1.0f + e2);
        g_tidx[tok * 2 + 0] = bi;  g_tw[tok * 2 + 0] = inv;
        g_tidx[tok * 2 + 1] = bi2; g_tw[tok * 2 + 1] = e2 * inv;
        atomicAdd(&g_counts[bi], 1);
        atomicAdd(&g_counts[bi2], 1);
    }

    // last finished gate block computes prefix sums + tile table
    __threadfence();
    __syncthreads();
    if (tid == 0)
        s_last = (atomicAdd(&g_gatefin, 1) == GBLK - 1) ? 1 : 0;
    __syncthreads();
    if (s_last && tid == 0) {
        int s = 0;
        #pragma unroll
        for (int e = 0; e < NE; ++e) { g_off[e] = s; s += g_counts[e]; }
        g_off[NE] = s;
        int nt = 0;
        for (int e = 0; e < NE; ++e)
            for (int m = g_off[e]; m < g_off[e + 1]; m += 128) {
                g_tile_e[nt] = e; g_tile_m[nt] = m; ++nt;
            }
        for (; nt < MAXT; ++nt) g_tile_e[nt] = -1;
    }
}

// ---------------- scatter (two-level, low contention) -------------------------
__global__ __launch_bounds__(256) void scatter_kernel() {
    __shared__ int lcnt[NE];
    __shared__ int lbase[NE];
    int tid = threadIdx.x;
    int tok = blockIdx.x * 256 + tid;
    if (tid < NE) lcnt[tid] = 0;
    __syncthreads();
    int e0 = g_tidx[tok * 2 + 0], e1 = g_tidx[tok * 2 + 1];
    int r0 = atomicAdd(&lcnt[e0], 1);
    int r1 = atomicAdd(&lcnt[e1], 1);
    __syncthreads();
    if (tid < NE) lbase[tid] = atomicAdd(&g_cursor[tid], lcnt[tid]);
    __syncthreads();
    g_perm[g_off[e0] + lbase[e0] + r0] = tok * 2 + 0;
    g_perm[g_off[e1] + lbase[e1] + r1] = tok * 2 + 1;
}

// ---------------- GEMM tile body (R6 core, frozen) ----------------------------
#define TS 40
#define ABUF_H (128 * TS)
#define STAGE_H (2 * ABUF_H)
#define GEMM_SMEM (2 * STAGE_H * 2)   // 40960 bytes

template <int K, int NTOT, int MODE>
__device__ __forceinline__ void process_tile(
    __half* smh, float* bias_s,
    int e, int m0, int mEnd, int n0,
    const float* __restrict__ Ap, const float* __restrict__ W,
    const float* __restrict__ bias, float* __restrict__ out)
{
    const int NC = K / 32;
    int tid = threadIdx.x, lane = tid & 31, wid = tid >> 5;
    int mw = (wid >> 2) * 64;
    int nw = (wid & 3) * 32;

    if (tid < 128) bias_s[tid] = bias[e * NTOT + n0 + tid];

    int brow = tid >> 3, bc4 = tid & 7;
    const float* bP[4];
    int bOff[4];
    #pragma unroll
    for (int i = 0; i < 4; ++i) {
        int row = brow + 32 * i;
        bP[i] = W + (size_t)e * NTOT * K + (size_t)(n0 + row) * K + bc4 * 4;
        bOff[i] = row * TS + bc4 * 4;
    }

    const float* aP[4];
    const __half* aPh[2];
    int aOff[4], aOffH[2];
    if (MODE == 0) {
        #pragma unroll
        for (int i = 0; i < 4; ++i) {
            int row = brow + 32 * i;
            int gRow = m0 + row;
            int cRow = (gRow < mEnd) ? gRow : m0;
            int pair = g_perm[cRow];
            aP[i] = Ap + (size_t)(pair >> 1) * K + bc4 * 4;
            aOff[i] = row * TS + bc4 * 4;
        }
    } else {
        int arow = tid >> 2, aseg = tid & 3;
        #pragma unroll
        for (int i = 0; i < 2; ++i) {
            int row = arow + 64 * i;
            int gRow = m0 + row;
            int cRow = (gRow < mEnd) ? gRow : m0;
            aPh[i] = g_h + (size_t)cRow * K + aseg * 8;
            aOffH[i] = row * TS + aseg * 8;
        }
    }

    uint32_t sb = (uint32_t)__cvta_generic_to_shared(smh);
    uint32_t aAddrBase = sb + (uint32_t)(((mw + (lane & 15)) * TS + (lane >> 4) * 8) * 2);
    int bg = lane >> 3;
    int nblk = bg >> 1, khalf = bg & 1;
    uint32_t bAddrBase = sb + (uint32_t)((ABUF_H +
        (nw + nblk * 8 + (lane & 7)) * TS + khalf * 8) * 2);

    float acc[4][4][4];
    #pragma unroll
    for (int mi = 0; mi < 4; ++mi)
        #pragma unroll
        for (int ni = 0; ni < 4; ++ni)
            #pragma unroll
            for (int j = 0; j < 4; ++j) acc[mi][ni][j] = 0.f;

    float4 pb[4];
    float4 pa[4];
    uint4 qa[2];

    #pragma unroll
    for (int i = 0; i < 4; ++i) pb[i] = *(const float4*)(bP[i]);
    if (MODE == 0) {
        #pragma unroll
        for (int i = 0; i < 4; ++i) pa[i] = *(const float4*)(aP[i]);
    } else {
        #pragma unroll
        for (int i = 0; i < 2; ++i) qa[i] = *(const uint4*)(aPh[i]);
    }
    {
        __half* sA = smh;
        __half* sB = smh + ABUF_H;
        #pragma unroll
        for (int i = 0; i < 4; ++i) {
            uint2 u = cvt2h(pb[i]);
            *(uint2*)(sB + bOff[i]) = u;
        }
        if (MODE == 0) {
            #pragma unroll
            for (int i = 0; i < 4; ++i) {
                uint2 u = cvt2h(pa[i]);
                *(uint2*)(sA + aOff[i]) = u;
            }
        } else {
            #pragma unroll
            for (int i = 0; i < 2; ++i) *(uint4*)(sA + aOffH[i]) = qa[i];
        }
    }
    __syncthreads();

    for (int s = 0; s < NC; ++s) {
        int b = s & 1;
        if (s + 1 < NC) {
            #pragma unroll
            for (int i = 0; i < 4; ++i) pb[i] = *(const float4*)(bP[i] + (s + 1) * 32);
            if (MODE == 0) {
                #pragma unroll
                for (int i = 0; i < 4; ++i) pa[i] = *(const float4*)(aP[i] + (s + 1) * 32);
            } else {
                #pragma unroll
                for (int i = 0; i < 2; ++i) qa[i] = *(const uint4*)(aPh[i] + (s + 1) * 32);
            }
        }
        uint32_t aA = aAddrBase + (uint32_t)(b * STAGE_H * 2);
        uint32_t bA = bAddrBase + (uint32_t)(b * STAGE_H * 2);
        #pragma unroll
        for (int ks = 0; ks < 2; ++ks) {
            uint32_t af[4][4];
            #pragma unroll
            for (int mi = 0; mi < 4; ++mi)
                ldsm4(aA + mi * (16 * TS * 2) + ks * 32, af[mi]);
            uint32_t bfr[8];
            #pragma unroll
            for (int ni2 = 0; ni2 < 2; ++ni2)
                ldsm4(bA + ni2 * (16 * TS * 2) + ks * 32, &bfr[ni2 * 4]);
            #pragma unroll
            for (int mi = 0; mi < 4; ++mi)
                #pragma unroll
                for (int ni = 0; ni < 4; ++ni)
                    mma_f16(acc[mi][ni], af[mi], &bfr[ni * 2]);
        }
        if (s + 1 < NC) {
            int nb = b ^ 1;
            __half* sA = smh + nb * STAGE_H;
            __half* sB = sA + ABUF_H;
            #pragma unroll
            for (int i = 0; i < 4; ++i) {
                uint2 u = cvt2h(pb[i]);
                *(uint2*)(sB + bOff[i]) = u;
            }
            if (MODE == 0) {
                #pragma unroll
                for (int i = 0; i < 4; ++i) {
                    uint2 u = cvt2h(pa[i]);
                    *(uint2*)(sA + aOff[i]) = u;
                }
            } else {
                #pragma unroll
                for (int i = 0; i < 2; ++i) *(uint4*)(sA + aOffH[i]) = qa[i];
            }
            __syncthreads();
        }
    }

    int r4 = lane >> 2, cc = (lane & 3) * 2;
    #pragma unroll
    for (int mi = 0; mi < 4; ++mi) {
        int row0 = m0 + mw + mi * 16 + r4;
        int row1 = row0 + 8;
        bool v0 = row0 < mEnd, v1 = row1 < mEnd;
        if (MODE == 0) {
            __half* C0 = g_h + (size_t)row0 * NTOT + n0;
            __half* C1 = g_h + (size_t)row1 * NTOT + n0;
            #pragma unroll
            for (int ni = 0; ni < 4; ++ni) {
                int col = nw + ni * 8 + cc;
                float bb0 = bias_s[col], bb1 = bias_s[col + 1];
                const float* d = acc[mi][ni];
                if (v0) {
                    __half2 h = __floats2half2_rn(fmaxf(d[0] + bb0, 0.f),
                                                  fmaxf(d[1] + bb1, 0.f));
                    *(__half2*)&C0[col] = h;
                }
                if (v1) {
                    __half2 h = __floats2half2_rn(fmaxf(d[2] + bb0, 0.f),
                                                  fmaxf(d[3] + bb1, 0.f));
                    *(__half2*)&C1[col] = h;
                }
            }
        } else {
            int p0 = 0, p1 = 0;
            float w0 = 0.f, w1 = 0.f;
            if (v0) { p0 = g_perm[row0]; w0 = g_tw[p0]; }
            if (v1) { p1 = g_perm[row1]; w1 = g_tw[p1]; }
            float* O0 = out + (size_t)(p0 >> 1) * DOUT + n0;
            float* O1 = out + (size_t)(p1 >> 1) * DOUT + n0;
            #pragma unroll
            for (int ni = 0; ni < 4; ++ni) {
                int col = nw + ni * 8 + cc;
                float bb0 = bias_s[col], bb1 = bias_s[col + 1];
                const float* d = acc[mi][ni];
                if (v0) red2(O0 + col, (d[0] + bb0) * w0, (d[1] + bb1) * w0);
                if (v1) red2(O1 + col, (d[2] + bb0) * w1, (d[3] + bb1) * w1);
            }
        }
    }
}

// ---------------- persistent fused GEMM1+GEMM2 (R13 ticket loop) --------------
__global__ __launch_bounds__(256, 2) void moe_gemm(const float* __restrict__ x,
                                                   const float* __restrict__ w1,
                                                   const float* __restrict__ b1,
                                                   const float* __restrict__ w2,
                                                   const float* __restrict__ b2,
                                                   float* __restrict__ out) {
    extern __shared__ __half smh[];
    __shared__ float bias_s[128];
    __shared__ int s_t;
    int tid = threadIdx.x;

    for (;;) {
        __syncthreads();                 // smem/bias_s reuse barrier
        if (tid == 0) s_t = atomicAdd(&g_ticket, 1);
        __syncthreads();
        int t = s_t;
        if (t >= TTOT) break;

        if (t < T1TOT) {
            int mt = t / NT1, nt = t % NT1;
            int e = g_tile_e[mt];
            if (e < 0) continue;
            int m0 = g_tile_m[mt];
            int mEnd = g_off[e + 1];
            process_tile<DI, DH, 0>(smh, bias_s, e, m0, mEnd, nt * 128,
                                    x, w1, b1, nullptr);
            __threadfence();             // publish g_h stores
            __syncthreads();
            if (tid == 0) atomicAdd(&g_done[mt], 1);
        } else {
            int idx = t - T1TOT;
            int mt = idx / NT2, nt = idx % NT2;
            int e = g_tile_e[mt];
            if (e < 0) continue;
            if (tid == 0) {
                while (*(volatile int*)&g_done[mt] < NT1) {}
                __threadfence();
            }
            __syncthreads();
            int m0 = g_tile_m[mt];
            int mEnd = g_off[e + 1];
            process_tile<DH, DOUT, 1>(smh, bias_s, e, m0, mEnd, nt * 128,
                                      nullptr, w2, b2, out);
        }
    }

    // last CTA resets control state for the next graph replay
    if (tid == 0) {
        int f = atomicAdd(&g_finish, 1);
        if (f == NCTA - 1) {
            #pragma unroll
            for (int i = 0; i < NE; ++i) { g_counts[i] = 0; g_cursor[i] = 0; }
            for (int i = 0; i < MAXT; ++i) g_done[i] = 0;
            g_ticket = 0;
            g_gatefin = 0;
            g_finish = 0;
            __threadfence();
        }
    }
}

// ---------------- launch -----------------------------------------------------
extern "C" void kernel_launch(void* const* d_in, const int* in_sizes, int n_in,
                              void* d_out, int out_size) {
    const float* x  = (const float*)d_in[0];
    const float* gw = (const float*)d_in[1];
    const float* w1 = (const float*)d_in[2];
    const float* b1 = (const float*)d_in[3];
    const float* w2 = (const float*)d_in[4];
    const float* b2 = (const float*)d_in[5];
    float* out = (float*)d_out;

    cudaFuncSetAttribute(gate_kernel,
                         cudaFuncAttributeMaxDynamicSharedMemorySize, GATE_SMEM);
    cudaFuncSetAttribute(moe_gemm,
                         cudaFuncAttributeMaxDynamicSharedMemorySize, GEMM_SMEM);

    gate_kernel<<<GBLK + ZB, 256, GATE_SMEM>>>(x, gw, out);
    scatter_kernel<<<NB / 256, 256>>>();
    moe_gemm<<<NCTA, 256, GEMM_SMEM>>>(x, w1, b1, w2, b2, out);
}